// round 1
// baseline (speedup 1.0000x reference)
#include <cuda_runtime.h>
#include <stdint.h>

#define N_LEVELS 16
#define BATCH (1 << 20)

// offsets into the embedding table (entry units, F=2 floats per entry)
__device__ __constant__ const int   kOffsets[N_LEVELS + 1] = {
    0, 4096, 12096, 27721, 60489, 124489, 249489, 511633, 1023633,
    1547921, 2072209, 2596497, 3120785, 3645073, 4169361, 4693649, 5217937};

// compile-time tables (used inside fully unrolled loop so everything folds)
__host__ __device__ __forceinline__ constexpr int lvl_res(int l) {
    constexpr int r[N_LEVELS] = {16, 20, 25, 32, 40, 50, 64, 80, 101, 128, 161, 203, 256, 322, 406, 512};
    return r[l];
}
__host__ __device__ __forceinline__ constexpr int lvl_off(int l) {
    constexpr int o[N_LEVELS + 1] = {0, 4096, 12096, 27721, 60489, 124489, 249489, 511633, 1023633,
                                     1547921, 2072209, 2596497, 3120785, 3645073, 4169361, 4693649, 5217937};
    return o[l];
}
__host__ __device__ __forceinline__ constexpr bool lvl_dense(int l) {
    // res^3 <= size  (true for levels 0..7, false for 8..15)
    long long r = lvl_res(l);
    long long size = lvl_off(l + 1) - lvl_off(l);
    return r * r * r <= size;
}

__global__ __launch_bounds__(256) void hashgrid_kernel(
    const float* __restrict__ xyz,
    const float2* __restrict__ emb,   // (5217937, 2) as float2
    const float* __restrict__ mn,
    const float* __restrict__ mx,
    float* __restrict__ out)
{
    const int b = blockIdx.x * blockDim.x + threadIdx.x;
    if (b >= BATCH) return;

    // normalize into [0,1] in the bbox
    const float inv_x = 1.0f / (mx[0] - mn[0]);
    const float inv_y = 1.0f / (mx[1] - mn[1]);
    const float inv_z = 1.0f / (mx[2] - mn[2]);
    const float xn = (xyz[3 * b + 0] - mn[0]) * inv_x;
    const float yn = (xyz[3 * b + 1] - mn[1]) * inv_y;
    const float zn = (xyz[3 * b + 2] - mn[2]) * inv_z;

    float* o = out + (size_t)b * (2 * N_LEVELS);

#pragma unroll
    for (int l = 0; l < N_LEVELS; ++l) {
        const int   res  = lvl_res(l);
        const int   off  = lvl_off(l);
        const bool  dense = lvl_dense(l);
        const uint32_t size = (uint32_t)(lvl_off(l + 1) - off); // 2^19 for hashed levels

        const float sc = (float)(res - 1);
        const float px = xn * sc;
        const float py = yn * sc;
        const float pz = zn * sc;

        float fx = floorf(px), fy = floorf(py), fz = floorf(pz);
        const float hi = (float)(res - 2);
        fx = fminf(fmaxf(fx, 0.0f), hi);
        fy = fminf(fmaxf(fy, 0.0f), hi);
        fz = fminf(fmaxf(fz, 0.0f), hi);

        const float wx = px - fx, wy = py - fy, wz = pz - fz;
        const uint32_t ix0 = (uint32_t)fx, iy0 = (uint32_t)fy, iz0 = (uint32_t)fz;

        // precompute the 8 global indices first -> 8 independent in-flight loads
        uint32_t idx[8];
#pragma unroll
        for (int c = 0; c < 8; ++c) {
            const uint32_t cx = (c >> 2) & 1u;
            const uint32_t cy = (c >> 1) & 1u;
            const uint32_t cz = c & 1u;
            const uint32_t x = ix0 + cx, y = iy0 + cy, z = iz0 + cz;
            uint32_t id;
            if (dense) {
                id = x * (uint32_t)(res * res) + y * (uint32_t)res + z;
            } else {
                id = (x * 1u) ^ (y * 2654435761u) ^ (z * 805459861u);
                id &= (size - 1u);   // size is a power of two (2^19) for all hashed levels
            }
            idx[c] = id;
        }

        float2 f[8];
#pragma unroll
        for (int c = 0; c < 8; ++c)
            f[c] = __ldg(emb + off + idx[c]);

        float a0 = 0.0f, a1 = 0.0f;
#pragma unroll
        for (int c = 0; c < 8; ++c) {
            const float mxw = ((c >> 2) & 1) ? wx : (1.0f - wx);
            const float myw = ((c >> 1) & 1) ? wy : (1.0f - wy);
            const float mzw = (c & 1)        ? wz : (1.0f - wz);
            const float w = mxw * myw * mzw;
            a0 = fmaf(w, f[c].x, a0);
            a1 = fmaf(w, f[c].y, a1);
        }
        o[2 * l + 0] = a0;
        o[2 * l + 1] = a1;
    }
}

extern "C" void kernel_launch(void* const* d_in, const int* in_sizes, int n_in,
                              void* d_out, int out_size)
{
    const float*  xyz = (const float*)d_in[0];
    const float2* emb = (const float2*)d_in[1];
    const float*  mn  = (const float*)d_in[2];
    const float*  mx  = (const float*)d_in[3];
    float* out = (float*)d_out;

    const int threads = 256;
    const int blocks  = (BATCH + threads - 1) / threads;
    hashgrid_kernel<<<blocks, threads>>>(xyz, emb, mn, mx, out);
}

// round 3
// speedup vs baseline: 1.5155x; 1.5155x over previous
#include <cuda_runtime.h>
#include <stdint.h>

#define N_LEVELS 16
#define BATCH (1 << 20)
#define DENSE_TOTAL 1023633   // sum of res^3 for levels 0..7 (== OFFSETS[8])

// z-pair-duplicated dense table: g_dense[i] = (emb[i].xy, emb[i+1].xy)
__device__ float4 g_dense[DENSE_TOTAL];

__host__ __device__ __forceinline__ constexpr int lvl_res(int l) {
    constexpr int r[N_LEVELS] = {16, 20, 25, 32, 40, 50, 64, 80, 101, 128, 161, 203, 256, 322, 406, 512};
    return r[l];
}
__host__ __device__ __forceinline__ constexpr int lvl_off(int l) {
    constexpr int o[N_LEVELS + 1] = {0, 4096, 12096, 27721, 60489, 124489, 249489, 511633, 1023633,
                                     1547921, 2072209, 2596497, 3120785, 3645073, 4169361, 4693649, 5217937};
    return o[l];
}
__host__ __device__ __forceinline__ constexpr bool lvl_dense(int l) {
    long long r = lvl_res(l);
    long long size = lvl_off(l + 1) - lvl_off(l);
    return r * r * r <= size;
}

// ── prologue: build z-pair dense table ─────────────────────────────────────
__global__ __launch_bounds__(256) void repack_kernel(const float2* __restrict__ emb)
{
    for (int i = blockIdx.x * blockDim.x + threadIdx.x; i < DENSE_TOTAL;
         i += gridDim.x * blockDim.x) {
        float2 a = __ldg(emb + i);
        float2 b = __ldg(emb + i + 1);   // i+1 <= 1023633 < 5217937, always in bounds
        g_dense[i] = make_float4(a.x, a.y, b.x, b.y);
    }
}

// ── main kernel ────────────────────────────────────────────────────────────
__global__ __launch_bounds__(256) void hashgrid_kernel(
    const float* __restrict__ xyz,
    const float2* __restrict__ emb,
    const float* __restrict__ mn,
    const float* __restrict__ mx,
    float* __restrict__ out)
{
    const int b = blockIdx.x * blockDim.x + threadIdx.x;
    if (b >= BATCH) return;

    const float inv_x = 1.0f / (mx[0] - mn[0]);
    const float inv_y = 1.0f / (mx[1] - mn[1]);
    const float inv_z = 1.0f / (mx[2] - mn[2]);
    const float xn = (xyz[3 * b + 0] - mn[0]) * inv_x;
    const float yn = (xyz[3 * b + 1] - mn[1]) * inv_y;
    const float zn = (xyz[3 * b + 2] - mn[2]) * inv_z;

    float4* o4 = (float4*)(out + (size_t)b * (2 * N_LEVELS));

    float pend0 = 0.0f, pend1 = 0.0f;  // accumulators of the even level in a pair

#pragma unroll
    for (int l = 0; l < N_LEVELS; ++l) {
        const int      res   = lvl_res(l);
        const int      off   = lvl_off(l);
        const bool     dense = lvl_dense(l);
        const uint32_t size  = (uint32_t)(lvl_off(l + 1) - off);  // 2^19 for hashed levels

        const float sc = (float)(res - 1);
        const float px = xn * sc, py = yn * sc, pz = zn * sc;

        float fx = floorf(px), fy = floorf(py), fz = floorf(pz);
        const float hi = (float)(res - 2);
        fx = fminf(fmaxf(fx, 0.0f), hi);
        fy = fminf(fmaxf(fy, 0.0f), hi);
        fz = fminf(fmaxf(fz, 0.0f), hi);

        const float wx = px - fx, wy = py - fy, wz = pz - fz;
        const uint32_t ix0 = (uint32_t)fx, iy0 = (uint32_t)fy, iz0 = (uint32_t)fz;

        float a0 = 0.0f, a1 = 0.0f;

        if (dense) {
            // 4 x LDG.128: each float4 holds corners (cz=0, cz=1) for a (cx,cy)
            const uint32_t r2 = (uint32_t)(res * res);
            uint32_t base[4];
#pragma unroll
            for (int c = 0; c < 4; ++c) {
                const uint32_t cx = (c >> 1) & 1u;
                const uint32_t cy = c & 1u;
                base[c] = (ix0 + cx) * r2 + (iy0 + cy) * (uint32_t)res + iz0;
            }
            float4 q[4];
#pragma unroll
            for (int c = 0; c < 4; ++c)
                q[c] = __ldg(&g_dense[off + base[c]]);

            const float omz = 1.0f - wz;
#pragma unroll
            for (int c = 0; c < 4; ++c) {
                const float mxw = ((c >> 1) & 1) ? wx : (1.0f - wx);
                const float myw = (c & 1)        ? wy : (1.0f - wy);
                const float wxy = mxw * myw;
                const float w0 = wxy * omz;  // cz = 0
                const float w1 = wxy * wz;   // cz = 1
                a0 = fmaf(w0, q[c].x, a0);
                a1 = fmaf(w0, q[c].y, a1);
                a0 = fmaf(w1, q[c].z, a0);
                a1 = fmaf(w1, q[c].w, a1);
            }
        } else {
            uint32_t idx[8];
#pragma unroll
            for (int c = 0; c < 8; ++c) {
                const uint32_t cx = (c >> 2) & 1u;
                const uint32_t cy = (c >> 1) & 1u;
                const uint32_t cz = c & 1u;
                uint32_t id = (ix0 + cx) ^ ((iy0 + cy) * 2654435761u) ^ ((iz0 + cz) * 805459861u);
                idx[c] = id & (size - 1u);   // size is 2^19 for all hashed levels
            }
            float2 f[8];
#pragma unroll
            for (int c = 0; c < 8; ++c)
                f[c] = __ldg(emb + off + idx[c]);

#pragma unroll
            for (int c = 0; c < 8; ++c) {
                const float mxw = ((c >> 2) & 1) ? wx : (1.0f - wx);
                const float myw = ((c >> 1) & 1) ? wy : (1.0f - wy);
                const float mzw = (c & 1)        ? wz : (1.0f - wz);
                const float w = mxw * myw * mzw;
                a0 = fmaf(w, f[c].x, a0);
                a1 = fmaf(w, f[c].y, a1);
            }
        }

        if ((l & 1) == 0) {
            pend0 = a0; pend1 = a1;
        } else {
            o4[l >> 1] = make_float4(pend0, pend1, a0, a1);  // one STG.128 per 2 levels
        }
    }
}

extern "C" void kernel_launch(void* const* d_in, const int* in_sizes, int n_in,
                              void* d_out, int out_size)
{
    const float*  xyz = (const float*)d_in[0];
    const float2* emb = (const float2*)d_in[1];
    const float*  mn  = (const float*)d_in[2];
    const float*  mx  = (const float*)d_in[3];
    float* out = (float*)d_out;

    repack_kernel<<<1024, 256>>>(emb);

    const int threads = 256;
    const int blocks  = (BATCH + threads - 1) / threads;
    hashgrid_kernel<<<blocks, threads>>>(xyz, emb, mn, mx, out);
}